// round 15
// baseline (speedup 1.0000x reference)
#include <cuda_runtime.h>
#include <stdint.h>
#include <math.h>

#define T_FRAMES 64
#define H_DIM 1024
#define W_DIM 1024
#define NPIX (H_DIM * W_DIM)
#define TPB 256
#define TPB_T 1024
#define FULLMASK 0xffffffffu

// sampling pass
#define SAMPLE_STRIDE 8
#define NSROWS (H_DIM / SAMPLE_STRIDE)      // 128 sample rows/frame
#define NSAMP (NSROWS * W_DIM)              // 131072 samples/frame
#define SH_BLOCKS 16
#define SH_ROWS (NSROWS / SH_BLOCKS)        // 8 sample rows per block

// main pass
#define MROWS 16
#define MCHUNKS (H_DIM / MROWS)             // 64 blocks per frame

#define CAP 65536
#define STCAP 2048
#define NSLICE 8

// population ranks (0-based), matching Python int() truncation
#define KG_RANK 891288u   // int(0.85*(NPIX-1))
#define KB_RANK 314572u   // int(0.30*(NPIX-1))
#define QG 0.85
#define QB 0.30
#define DMARG 0.005       // ~5 sigma of sampling error at NSAMP=131072

// ---------------- device scratch ----------------
__device__ unsigned g_histG[T_FRAMES][4096];
__device__ unsigned g_histB[T_FRAMES][4096];
__device__ int4     g_sel[T_FRAMES];          // {Lg, Hg, Lb, Hb}
__device__ unsigned g_cntG[T_FRAMES];
__device__ unsigned g_cntB[T_FRAMES];
__device__ unsigned g_aux[T_FRAMES][2];       // [0]=count(kg>=HgB), [1]=count(kb<LbB)
__device__ unsigned g_h16[T_FRAMES][2][16];   // exact per-bin counts inside bracket
__device__ unsigned g_thr[T_FRAMES][2];       // {thrG_eff (gm2 key), thrB (|f| key)}
__device__ double   g_acc[T_FRAMES][4];       // cnt, sum(gm), sum(gm*x), sum(gm*y)
// SoA candidate buffers (16B-aligned rows for uint4 scans)
__device__ __align__(16) unsigned g_keyG[T_FRAMES][CAP];    // gm2 key
__device__ __align__(16) unsigned g_othG[T_FRAMES][CAP];    // |f| key
__device__ __align__(16) unsigned g_xyG [T_FRAMES][CAP];
__device__ __align__(16) unsigned g_keyB[T_FRAMES][CAP];    // |f| key
__device__ __align__(16) unsigned g_othB[T_FRAMES][CAP];    // gm2 key
__device__ __align__(16) unsigned g_xyB [T_FRAMES][CAP];

// ---------------- K0: zero scratch --------------------------------------------
__global__ void k_zero() {
    int i = blockIdx.x * blockDim.x + threadIdx.x;
    if (i < T_FRAMES * 4096) {
        ((unsigned*)g_histG)[i] = 0;
        ((unsigned*)g_histB)[i] = 0;
    }
    if (i < T_FRAMES * 32) ((unsigned*)g_h16)[i] = 0;
    if (i < T_FRAMES) {
        g_cntG[i] = 0; g_cntB[i] = 0;
        g_aux[i][0] = 0; g_aux[i][1] = 0;
        g_acc[i][0] = 0.0; g_acc[i][1] = 0.0; g_acc[i][2] = 0.0; g_acc[i][3] = 0.0;
    }
}

// ------ K1: SAMPLED top-12-bit histograms, lane-parity-replicated, 2 phases -----
// Intra-warp same-bin atomic conflicts are the bottleneck (clustered normal
// keys); replica by lane parity halves the per-address conflict degree while
// keeping smem at 32KB via two sequential phases (G keys, then B keys).
__global__ void __launch_bounds__(TPB) k_shist(const float* __restrict__ frames) {
    __shared__ unsigned h[2][4096];
    const int t = blockIdx.y;
    const float* __restrict__ f = frames + (size_t)t * NPIX;
    const int x0 = threadIdx.x * 4;
    const int lane = threadIdx.x & 31;
    const int rep = lane & 1;
    const bool notLast = (threadIdx.x < TPB - 1);

    // ---- phase G: gm2 keys ----
    for (int i = threadIdx.x; i < 8192; i += TPB) ((unsigned*)h)[i] = 0;
    __syncthreads();
    for (int s = 0; s < SH_ROWS; s++) {
        const int y = (blockIdx.x * SH_ROWS + s) * SAMPLE_STRIDE;   // <= 1016
        const int p = y * W_DIM + x0;
        float4 a = *(const float4*)(f + p);
        float4 b = *(const float4*)(f + p + W_DIM);   // y+1 valid
        float nx = __shfl_down_sync(FULLMASK, a.x, 1);
        if (lane == 31) nx = notLast ? f[p + 4] : 0.0f;

        float av[4] = {a.x, a.y, a.z, a.w};
        float bv[4] = {b.x, b.y, b.z, b.w};
        #pragma unroll
        for (int j = 0; j < 4; j++) {
            float gx = (j < 3) ? __fadd_rn(av[j + 1], -av[j])
                               : (notLast ? __fadd_rn(nx, -av[3]) : 0.0f);
            float gy = __fadd_rn(bv[j], -av[j]);
            float gm2 = __fadd_rn(__fmul_rn(gx, gx), __fmul_rn(gy, gy));
            atomicAdd(&h[rep][__float_as_uint(gm2) >> 20], 1u);
        }
    }
    __syncthreads();
    for (int i = threadIdx.x; i < 4096; i += TPB) {
        unsigned v = h[0][i] + h[1][i];
        if (v) atomicAdd(&g_histG[t][i], v);
    }
    __syncthreads();

    // ---- phase B: |f| keys (current row only; reload is L1-resident) ----
    for (int i = threadIdx.x; i < 8192; i += TPB) ((unsigned*)h)[i] = 0;
    __syncthreads();
    for (int s = 0; s < SH_ROWS; s++) {
        const int y = (blockIdx.x * SH_ROWS + s) * SAMPLE_STRIDE;
        float4 a = *(const float4*)(f + y * W_DIM + x0);
        float av[4] = {a.x, a.y, a.z, a.w};
        #pragma unroll
        for (int j = 0; j < 4; j++)
            atomicAdd(&h[rep][__float_as_uint(fabsf(av[j])) >> 20], 1u);
    }
    __syncthreads();
    for (int i = threadIdx.x; i < 4096; i += TPB) {
        unsigned v = h[0][i] + h[1][i];
        if (v) atomicAdd(&g_histB[t][i], v);
    }
}

// ------------- "which bin holds rank K" (256 workers, blockDim>=256) ------------
template <int NBINS>
__device__ __forceinline__ void kth_bin(unsigned* h, unsigned K, unsigned* toff,
                                        int* s_bin, unsigned* s_rem) {
    const int seg = NBINS / 256;
    const int tid = threadIdx.x;
    const bool act = (tid < 256);
    if (tid == 0) { *s_bin = 0; *s_rem = 0; }
    unsigned s = 0;
    const int base = tid * seg;
    if (act) {
        #pragma unroll
        for (int i = 0; i < seg; i++) s += h[base + i];
        toff[tid] = s;
    }
    __syncthreads();
    if (tid == 0) {
        unsigned run = 0;
        for (int i = 0; i < 256; i++) { unsigned v = toff[i]; toff[i] = run; run += v; }
    }
    __syncthreads();
    if (act) {
        unsigned off = toff[tid];
        if (K >= off && K < off + s) {
            unsigned run = off;
            for (int i = 0; i < seg; i++) {
                unsigned c = h[base + i];
                if (K < run + c) { *s_bin = base + i; *s_rem = K - run; break; }
                run += c;
            }
        }
    }
    __syncthreads();
}

// ---------------- K2: bracket bins from sample histogram ------------------------
__global__ void __launch_bounds__(TPB) k_bracket() {
    __shared__ unsigned h[4096];
    __shared__ unsigned toff[256];
    __shared__ int s_bin;
    __shared__ unsigned s_rem;
    const int t = blockIdx.x;
    const double nm1 = (double)(NSAMP - 1);
    for (int which = 0; which < 2; which++) {
        const unsigned* src = which ? g_histB[t] : g_histG[t];
        const double q = which ? QB : QG;
        for (int i = threadIdx.x; i < 4096; i += TPB) h[i] = src[i];
        __syncthreads();
        unsigned klo = (unsigned)((q - DMARG) * nm1);
        unsigned khi = (unsigned)((q + DMARG) * nm1) + 1u;
        if (khi > (unsigned)(NSAMP - 1)) khi = (unsigned)(NSAMP - 1);
        kth_bin<4096>(h, klo, toff, &s_bin, &s_rem);
        int L0 = s_bin;
        __syncthreads();
        kth_bin<4096>(h, khi, toff, &s_bin, &s_rem);
        int H0 = s_bin;
        if (threadIdx.x == 0) {
            int L = L0;
            int H = H0;
            if (H > L + 15) H = L + 15;      // mini-hist width cap
            if (H < L) H = L;
            if (which == 0) { g_sel[t].x = L; g_sel[t].y = H; }
            else            { g_sel[t].z = L; g_sel[t].w = H; }
        }
        __syncthreads();
    }
}

// ------------- cold path: staging overflow -> direct global append --------------
__device__ __noinline__ void overflow_push(int t, bool inG, bool inB,
                                           unsigned kg, unsigned kb, unsigned xy,
                                           int Lg, int Lb) {
    if (inG) {
        unsigned g = atomicAdd(&g_cntG[t], 1u);
        if (g < CAP) { g_keyG[t][g] = kg; g_othG[t][g] = kb; g_xyG[t][g] = xy; }
        atomicAdd(&g_h16[t][0][(kg >> 20) - (unsigned)Lg], 1u);
    }
    if (inB) {
        unsigned g = atomicAdd(&g_cntB[t], 1u);
        if (g < CAP) { g_keyB[t][g] = kb; g_othB[t][g] = kg; g_xyB[t][g] = xy; }
        atomicAdd(&g_h16[t][1][(kb >> 20) - (unsigned)Lb], 1u);
    }
}

struct Acc { int cnt, nA, nBB; float sgA0, sgA1, sgA2, sgA3, sgy; };

// -------- hot row body: consumes preloaded a (this row) and b (row below) -------
template <bool HB>
__device__ __forceinline__ void row_body(
    const float* __restrict__ f, int t, int y, int x0, int lane, bool notLast,
    unsigned LgB, unsigned HgB, unsigned LbB, unsigned HbB, int Lg, int Lb,
    const float4& a, const float4& b, Acc& ac,
    unsigned* stK1, unsigned* stK2, unsigned* stX, unsigned* s_cnt)
{
    float nx = __shfl_down_sync(FULLMASK, a.x, 1);
    if (lane == 31) nx = notLast ? f[y * W_DIM + x0 + 4] : 0.0f;
    const float yf = (float)y;
    const unsigned xyb = (unsigned)((y << 10) | x0);
    float av[4] = {a.x, a.y, a.z, a.w};
    float bv[4] = {b.x, b.y, b.z, b.w};
    #pragma unroll
    for (int j = 0; j < 4; j++) {
        float gx = (j < 3) ? __fadd_rn(av[j + 1], -av[j])
                           : (notLast ? __fadd_rn(nx, -av[3]) : 0.0f);
        float gm2;
        if (HB) {
            float gy = __fadd_rn(bv[j], -av[j]);
            gm2 = __fadd_rn(__fmul_rn(gx, gx), __fmul_rn(gy, gy));
        } else {
            gm2 = __fadd_rn(__fmul_rn(gx, gx), 0.0f);
        }
        unsigned kg = __float_as_uint(gm2);
        unsigned kb = __float_as_uint(fabsf(av[j]));
        bool aboveG = (kg >= HgB);
        bool belowB = (kb < LbB);
        ac.nA  += aboveG;
        ac.nBB += belowB;
        // branchless definite-masked accumulation (approx sqrt: 1 MUFU)
        float gm;
        asm("sqrt.approx.f32 %0, %1;" : "=f"(gm) : "f"(gm2));
        bool def = aboveG & belowB;
        float w = def ? gm : 0.0f;
        ac.cnt += def;
        if (j == 0) ac.sgA0 += w;
        if (j == 1) ac.sgA1 += w;
        if (j == 2) ac.sgA2 += w;
        if (j == 3) ac.sgA3 += w;
        ac.sgy += w * yf;
        bool inG = (kg >= LgB) & !aboveG;
        bool inB = !belowB & (kb < HbB);
        if (inG | inB) {
            unsigned fl = (inG ? 0x80000000u : 0u) | (inB ? 0x40000000u : 0u);
            unsigned idx = atomicAdd(s_cnt, 1u);
            if (idx < STCAP) {
                stK1[idx] = kg; stK2[idx] = kb; stX[idx] = (xyb | (unsigned)j) | fl;
            } else {
                overflow_push(t, inG, inB, kg, kb, xyb | (unsigned)j, Lg, Lb);
            }
        }
    }
}

// ------- K3: single full pass: counts + definite sums + compaction --------------
// Software-pipelined rows: prefetch row y+2 while computing row y.
__global__ void __launch_bounds__(TPB) k_main(const float* __restrict__ frames) {
    __shared__ unsigned stK1[STCAP], stK2[STCAP], stX[STCAP];
    __shared__ unsigned s_cnt;
    __shared__ unsigned h16G[16], h16B[16];
    if (threadIdx.x == 0) s_cnt = 0;
    if (threadIdx.x < 16) { h16G[threadIdx.x] = 0; h16B[threadIdx.x] = 0; }
    __syncthreads();

    const int t = blockIdx.y;
    const int4 sel = g_sel[t];
    const int Lg = sel.x, Hg = sel.y, Lb = sel.z, Hb = sel.w;
    const unsigned LgB = (unsigned)Lg << 20;
    const unsigned HgB = (Hg >= 4095) ? 0xFFFFFFFFu : ((unsigned)(Hg + 1) << 20);
    const unsigned LbB = (unsigned)Lb << 20;
    const unsigned HbB = (Hb >= 4095) ? 0xFFFFFFFFu : ((unsigned)(Hb + 1) << 20);
    const float* __restrict__ f = frames + (size_t)t * NPIX;
    const int row0 = blockIdx.x * MROWS;
    const int x0 = threadIdx.x * 4;
    const int lane = threadIdx.x & 31;
    const bool notLast = (threadIdx.x < TPB - 1);

    Acc ac = {0, 0, 0, 0.f, 0.f, 0.f, 0.f, 0.f};
    float4 a = *(const float4*)(f + row0 * W_DIM + x0);          // row y
    float4 b = *(const float4*)(f + (row0 + 1) * W_DIM + x0);    // row y+1

    if (row0 + MROWS < H_DIM) {
        #pragma unroll 1
        for (int r = 0; r < MROWS; r++) {
            const int y = row0 + r;
            float4 bn = *(const float4*)(f + (y + 2) * W_DIM + x0);   // prefetch
            row_body<true>(f, t, y, x0, lane, notLast,
                           LgB, HgB, LbB, HbB, Lg, Lb, a, b, ac,
                           stK1, stK2, stX, &s_cnt);
            a = b; b = bn;
        }
    } else {
        #pragma unroll 1
        for (int r = 0; r < MROWS - 1; r++) {
            const int y = row0 + r;
            float4 bn = (y + 2 <= H_DIM - 1)
                        ? *(const float4*)(f + (y + 2) * W_DIM + x0)
                        : make_float4(0.f, 0.f, 0.f, 0.f);
            row_body<true>(f, t, y, x0, lane, notLast,
                           LgB, HgB, LbB, HbB, Lg, Lb, a, b, ac,
                           stK1, stK2, stX, &s_cnt);
            a = b; b = bn;
        }
        row_body<false>(f, t, H_DIM - 1, x0, lane, notLast,
                        LgB, HgB, LbB, HbB, Lg, Lb, a, b, ac,
                        stK1, stK2, stX, &s_cnt);
    }

    // ---- flush staged candidates: mini-hist + warp-aggregated global append ----
    __syncthreads();
    unsigned n = s_cnt; if (n > STCAP) n = STCAP;
    for (unsigned base = 0; base < n; base += TPB) {
        unsigned i = base + threadIdx.x;
        bool act = (i < n);
        unsigned k1 = 0, k2 = 0, x = 0;
        bool inG = false, inB = false;
        if (act) {
            k1 = stK1[i]; k2 = stK2[i]; x = stX[i];
            inG = (x >> 31) != 0; inB = ((x >> 30) & 1u) != 0;
            x &= 0xFFFFFu;
        }
        if (act && inG) atomicAdd(&h16G[(k1 >> 20) - (unsigned)Lg], 1u);
        if (act && inB) atomicAdd(&h16B[(k2 >> 20) - (unsigned)Lb], 1u);

        unsigned m = __ballot_sync(FULLMASK, act && inG);
        if (m) {
            int leader = __ffs(m) - 1;
            unsigned bp = 0;
            if (lane == leader) bp = atomicAdd(&g_cntG[t], (unsigned)__popc(m));
            bp = __shfl_sync(FULLMASK, bp, leader);
            if (act && inG) {
                unsigned d = bp + (unsigned)__popc(m & ((1u << lane) - 1u));
                if (d < CAP) { g_keyG[t][d] = k1; g_othG[t][d] = k2; g_xyG[t][d] = x; }
            }
        }
        m = __ballot_sync(FULLMASK, act && inB);
        if (m) {
            int leader = __ffs(m) - 1;
            unsigned bp = 0;
            if (lane == leader) bp = atomicAdd(&g_cntB[t], (unsigned)__popc(m));
            bp = __shfl_sync(FULLMASK, bp, leader);
            if (act && inB) {
                unsigned d = bp + (unsigned)__popc(m & ((1u << lane) - 1u));
                if (d < CAP) { g_keyB[t][d] = k2; g_othB[t][d] = k1; g_xyB[t][d] = x; }
            }
        }
    }
    __syncthreads();
    if (threadIdx.x < 16) {
        unsigned v = h16G[threadIdx.x];
        if (v) atomicAdd(&g_h16[t][0][threadIdx.x], v);
        v = h16B[threadIdx.x];
        if (v) atomicAdd(&g_h16[t][1][threadIdx.x], v);
    }

    // ---- reconstruct sums, warp reduce, one atomic set per warp ----
    int cnt = ac.cnt, nA = ac.nA, nBB = ac.nBB;
    float sg  = ((ac.sgA0 + ac.sgA1) + (ac.sgA2 + ac.sgA3));
    float sgx = (float)x0 * sg + (ac.sgA1 + 2.0f * ac.sgA2 + 3.0f * ac.sgA3);
    float sgy = ac.sgy;
    #pragma unroll
    for (int o = 16; o; o >>= 1) {
        cnt += __shfl_down_sync(FULLMASK, cnt, o);
        nA  += __shfl_down_sync(FULLMASK, nA,  o);
        nBB += __shfl_down_sync(FULLMASK, nBB, o);
        sg  += __shfl_down_sync(FULLMASK, sg,  o);
        sgx += __shfl_down_sync(FULLMASK, sgx, o);
        sgy += __shfl_down_sync(FULLMASK, sgy, o);
    }
    if (lane == 0) {
        atomicAdd(&g_aux[t][0], (unsigned)nA);
        atomicAdd(&g_aux[t][1], (unsigned)nBB);
        atomicAdd(&g_acc[t][0], (double)cnt);
        atomicAdd(&g_acc[t][1], (double)sg);
        atomicAdd(&g_acc[t][2], (double)sgx);
        atomicAdd(&g_acc[t][3], (double)sgy);
    }
}

// ------- K4a: exact thresholds (2 vectorized buffer passes, 1024 threads) -------
__global__ void __launch_bounds__(TPB_T) k_thresh() {
    __shared__ unsigned h[4096];
    __shared__ unsigned toff[256];
    __shared__ int s_bin;
    __shared__ unsigned s_rem;
    __shared__ int sh_b1;
    __shared__ unsigned sh_r1;
    const int t = blockIdx.x;
    const int w = blockIdx.y;                 // 0 = G(gm2), 1 = B(|f|)
    const unsigned* __restrict__ key = w ? g_keyB[t] : g_keyG[t];
    const unsigned cnt = min(w ? g_cntB[t] : g_cntG[t], (unsigned)CAP);
    const int L = w ? g_sel[t].z : g_sel[t].x;
    const int tid = threadIdx.x;

    if (tid == 0) {
        long long below;
        if (w == 0) {
            // belowG = NPIX - inG_exact - aboveG_exact
            below = (long long)NPIX - (long long)g_cntG[t] - (long long)g_aux[t][0];
        } else {
            below = (long long)g_aux[t][1];
        }
        long long r = (long long)(w ? KB_RANK : KG_RANK) - below;
        if (r < 0) r = 0;
        if (r > (long long)cnt - 1) r = (long long)cnt - 1;
        unsigned run = 0; int b1 = L; unsigned r1 = (unsigned)r;
        for (int i = 0; i < 16; i++) {
            unsigned c = g_h16[t][w][i];
            if ((unsigned)r < run + c) { b1 = L + i; r1 = (unsigned)r - run; break; }
            run += c;
        }
        sh_b1 = b1; sh_r1 = r1;
    }
    __syncthreads();
    const unsigned b1 = (unsigned)sh_b1;
    const unsigned r1 = sh_r1;

    const unsigned nv4 = cnt >> 2;
    const unsigned tail = nv4 << 2;
    const uint4* __restrict__ key4 = (const uint4*)key;

    // level 1: bits 8..19 within bin b1
    for (int i = tid; i < 4096; i += TPB_T) h[i] = 0;
    __syncthreads();
    for (unsigned u = tid; u < nv4; u += TPB_T) {
        uint4 k4 = key4[u];
        if ((k4.x >> 20) == b1) atomicAdd(&h[(k4.x >> 8) & 0xFFFu], 1u);
        if ((k4.y >> 20) == b1) atomicAdd(&h[(k4.y >> 8) & 0xFFFu], 1u);
        if ((k4.z >> 20) == b1) atomicAdd(&h[(k4.z >> 8) & 0xFFFu], 1u);
        if ((k4.w >> 20) == b1) atomicAdd(&h[(k4.w >> 8) & 0xFFFu], 1u);
    }
    if ((unsigned)tid < cnt - tail) {
        unsigned k = key[tail + tid];
        if ((k >> 20) == b1) atomicAdd(&h[(k >> 8) & 0xFFFu], 1u);
    }
    __syncthreads();
    kth_bin<4096>(h, r1, toff, &s_bin, &s_rem);
    int b2 = s_bin; unsigned r2 = s_rem;
    __syncthreads();
    // level 2: low 8 bits
    for (int i = tid; i < 256; i += TPB_T) h[i] = 0;
    __syncthreads();
    unsigned pref = (b1 << 12) | (unsigned)b2;
    for (unsigned u = tid; u < nv4; u += TPB_T) {
        uint4 k4 = key4[u];
        if ((k4.x >> 8) == pref) atomicAdd(&h[k4.x & 0xFFu], 1u);
        if ((k4.y >> 8) == pref) atomicAdd(&h[k4.y & 0xFFu], 1u);
        if ((k4.z >> 8) == pref) atomicAdd(&h[k4.z & 0xFFu], 1u);
        if ((k4.w >> 8) == pref) atomicAdd(&h[k4.w & 0xFFu], 1u);
    }
    if ((unsigned)tid < cnt - tail) {
        unsigned k = key[tail + tid];
        if ((k >> 8) == pref) atomicAdd(&h[k & 0xFFu], 1u);
    }
    __syncthreads();
    kth_bin<256>(h, r2, toff, &s_bin, &s_rem);
    unsigned thr = (pref << 8) | (unsigned)s_bin;
    if (tid == 0) {
        if (w == 0) {
            // widen: reference mask is sqrtf(gm2) > sqrtf(thr2)
            float s = __fsqrt_rn(__uint_as_float(thr));
            unsigned k = thr;
            for (int i = 0; i < 64; i++) {
                if (__fsqrt_rn(__uint_as_float(k + 1u)) == s) k++;
                else break;
            }
            g_thr[t][0] = k;
        } else {
            g_thr[t][1] = thr;
        }
    }
}

// ---------------- K4b: resolve ambiguous pixels exactly (vectorized) ------------
__global__ void __launch_bounds__(TPB) k_apply() {
    const int t = blockIdx.x;
    const int q = blockIdx.y;            // NSLICE slices per frame
    const unsigned thrG = g_thr[t][0];
    const unsigned thrB = g_thr[t][1];
    const unsigned Hg = (unsigned)g_sel[t].y;
    const unsigned cG = min(g_cntG[t], (unsigned)CAP);
    const unsigned cB = min(g_cntB[t], (unsigned)CAP);

    int   cnt = 0;
    float sg = 0.f, sgx = 0.f, sgy = 0.f;

    // --- G side ---
    {
        const uint4* __restrict__ k4p = (const uint4*)g_keyG[t];
        const uint4* __restrict__ o4p = (const uint4*)g_othG[t];
        const unsigned nv4 = cG >> 2, tail = nv4 << 2;
        for (unsigned u = q * TPB + threadIdx.x; u < nv4; u += TPB * NSLICE) {
            uint4 k4 = k4p[u];
            uint4 o4 = o4p[u];
            unsigned kk[4] = {k4.x, k4.y, k4.z, k4.w};
            unsigned oo[4] = {o4.x, o4.y, o4.z, o4.w};
            #pragma unroll
            for (int j = 0; j < 4; j++) {
                if (kk[j] > thrG && oo[j] < thrB) {
                    unsigned xy = g_xyG[t][u * 4 + j];
                    float gm = __fsqrt_rn(__uint_as_float(kk[j]));
                    cnt++;
                    sg  += gm;
                    sgx += gm * (float)(xy & 1023u);
                    sgy += gm * (float)(xy >> 10);
                }
            }
        }
        if (q == 0 && (unsigned)threadIdx.x < cG - tail) {
            unsigned i = tail + threadIdx.x;
            unsigned k = g_keyG[t][i], o = g_othG[t][i];
            if (k > thrG && o < thrB) {
                unsigned xy = g_xyG[t][i];
                float gm = __fsqrt_rn(__uint_as_float(k));
                cnt++;
                sg  += gm;
                sgx += gm * (float)(xy & 1023u);
                sgy += gm * (float)(xy >> 10);
            }
        }
    }
    // --- B side (only pixels with gbin strictly above the G bracket) ---
    {
        const uint4* __restrict__ k4p = (const uint4*)g_keyB[t];
        const uint4* __restrict__ o4p = (const uint4*)g_othB[t];
        const unsigned nv4 = cB >> 2, tail = nv4 << 2;
        for (unsigned u = q * TPB + threadIdx.x; u < nv4; u += TPB * NSLICE) {
            uint4 k4 = k4p[u];
            uint4 o4 = o4p[u];
            unsigned kk[4] = {k4.x, k4.y, k4.z, k4.w};
            unsigned oo[4] = {o4.x, o4.y, o4.z, o4.w};
            #pragma unroll
            for (int j = 0; j < 4; j++) {
                if ((oo[j] >> 20) > Hg && oo[j] > thrG && kk[j] < thrB) {
                    unsigned xy = g_xyB[t][u * 4 + j];
                    float gm = __fsqrt_rn(__uint_as_float(oo[j]));
                    cnt++;
                    sg  += gm;
                    sgx += gm * (float)(xy & 1023u);
                    sgy += gm * (float)(xy >> 10);
                }
            }
        }
        if (q == 0 && (unsigned)threadIdx.x < cB - tail) {
            unsigned i = tail + threadIdx.x;
            unsigned k = g_keyB[t][i], o = g_othB[t][i];
            if ((o >> 20) > Hg && o > thrG && k < thrB) {
                unsigned xy = g_xyB[t][i];
                float gm = __fsqrt_rn(__uint_as_float(o));
                cnt++;
                sg  += gm;
                sgx += gm * (float)(xy & 1023u);
                sgy += gm * (float)(xy >> 10);
            }
        }
    }
    #pragma unroll
    for (int o = 16; o; o >>= 1) {
        cnt += __shfl_down_sync(FULLMASK, cnt, o);
        sg  += __shfl_down_sync(FULLMASK, sg,  o);
        sgx += __shfl_down_sync(FULLMASK, sgx, o);
        sgy += __shfl_down_sync(FULLMASK, sgy, o);
    }
    if ((threadIdx.x & 31) == 0) {
        atomicAdd(&g_acc[t][0], (double)cnt);
        atomicAdd(&g_acc[t][1], (double)sg);
        atomicAdd(&g_acc[t][2], (double)sgx);
        atomicAdd(&g_acc[t][3], (double)sgy);
    }
}

// ------------- block reduction over 64 doubles (64 threads) ---------------------
__device__ __forceinline__ double bred64(double v, double* red) {
    int t = threadIdx.x;
    red[t] = v;
    __syncthreads();
    for (int s = 32; s > 0; s >>= 1) {
        if (t < s) red[t] += red[t + s];
        __syncthreads();
    }
    double r = red[0];
    __syncthreads();
    return r;
}

// ---------------- K5: depthwise conv + final 8 stats (64 threads) ---------------
__global__ void k_final(const float* __restrict__ conv_w,
                        const float* __restrict__ conv_b,
                        float* __restrict__ out) {
    __shared__ double sst[4][T_FRAMES];
    __shared__ double sy[4][T_FRAMES];
    __shared__ double red[T_FRAMES];
    const int t = threadIdx.x;   // 64 threads
    const int n = T_FRAMES;
    {
        double c = g_acc[t][0], sg = g_acc[t][1], sgx = g_acc[t][2], sgy = g_acc[t][3];
        double pil = c < 1e-6 ? 1e-6 : c;
        double ws  = sg < 1e-6 ? 1e-6 : sg;
        sst[0][t] = c / (double)NPIX;
        sst[1][t] = sg / pil;
        sst[2][t] = sgx / ws / (double)W_DIM;
        sst[3][t] = sgy / ws / (double)H_DIM;
    }
    __syncthreads();
    #pragma unroll
    for (int c = 0; c < 4; c++) {
        double v = (double)conv_b[c] + (double)conv_w[c * 3 + 1] * sst[c][t];
        if (t > 0)     v += (double)conv_w[c * 3 + 0] * sst[c][t - 1];
        if (t < n - 1) v += (double)conv_w[c * 3 + 2] * sst[c][t + 1];
        sy[c][t] = v;
    }
    __syncthreads();

    double lm = bred64(sy[0][t], red) / n;
    double im = bred64(sy[1][t], red) / n;
    double tn = (double)t / (double)(n - 1) - 0.5;
    double lt  = bred64((sy[0][t] - lm) * tn, red) * 6.0 / n;
    double itr = bred64((sy[1][t] - im) * tn, red) * 6.0 / n;

    double dx = 0.0, dy = 0.0, sp = 0.0;
    if (t < n - 1) {
        dx = sy[2][t + 1] - sy[2][t];
        dy = sy[3][t + 1] - sy[3][t];
        sp = sqrt(dx * dx + dy * dy);
    }
    double sdx  = bred64(dx, red);
    double sdy  = bred64(dy, red);
    double ssum = bred64(sp, red);
    double ms = ssum / (double)(n - 1);
    double var = bred64(t < n - 1 ? (sp - ms) * (sp - ms) : 0.0, red) / (double)(n - 2);

    if (t == 0) {
        out[0] = (float)lm;
        out[1] = (float)lt;
        out[2] = (float)im;
        out[3] = (float)itr;
        out[4] = (float)ms;
        out[5] = (float)(atan2(sdy, sdx) / 3.14159265358979323846);
        out[6] = (float)((sy[0][n - 1] - sy[0][0]) / (double)(n - 1));
        out[7] = (float)sqrt(var);
    }
}

// ---------------- entry point -----------------------------------------------------
extern "C" void kernel_launch(void* const* d_in, const int* in_sizes, int n_in,
                              void* d_out, int out_size) {
    const float* frames = (const float*)d_in[0];
    // d_in[1] = observed_mask (unused by reference)
    const float* conv_w = (const float*)d_in[2];
    const float* conv_b = (const float*)d_in[3];
    float* out = (float*)d_out;

    k_zero<<<(T_FRAMES * 4096 + TPB - 1) / TPB, TPB>>>();
    k_shist<<<dim3(SH_BLOCKS, T_FRAMES), TPB>>>(frames);
    k_bracket<<<T_FRAMES, TPB>>>();
    k_main<<<dim3(MCHUNKS, T_FRAMES), TPB>>>(frames);
    k_thresh<<<dim3(T_FRAMES, 2), TPB_T>>>();
    k_apply<<<dim3(T_FRAMES, NSLICE), TPB>>>();
    k_final<<<1, T_FRAMES>>>(conv_w, conv_b, out);
}

// round 16
// speedup vs baseline: 1.0218x; 1.0218x over previous
#include <cuda_runtime.h>
#include <stdint.h>
#include <math.h>

#define T_FRAMES 64
#define H_DIM 1024
#define W_DIM 1024
#define NPIX (H_DIM * W_DIM)
#define TPB 256
#define TPB_T 1024
#define FULLMASK 0xffffffffu

// sampling pass
#define SAMPLE_STRIDE 8
#define NSROWS (H_DIM / SAMPLE_STRIDE)      // 128 sample rows/frame
#define NSAMP (NSROWS * W_DIM)              // 131072 samples/frame
#define SH_BLOCKS 16
#define SH_ROWS (NSROWS / SH_BLOCKS)        // 8 sample rows per block

// main pass
#define MROWS 16
#define MCHUNKS (H_DIM / MROWS)             // 64 blocks per frame

#define CAP 65536
#define STCAP 2048
#define NSLICE 16

// population ranks (0-based), matching Python int() truncation
#define KG_RANK 891288u   // int(0.85*(NPIX-1))
#define KB_RANK 314572u   // int(0.30*(NPIX-1))
#define QG 0.85
#define QB 0.30
#define DMARG 0.005       // ~5 sigma of sampling error at NSAMP=131072

// ---------------- device scratch ----------------
__device__ unsigned g_histG[T_FRAMES][4096];
__device__ unsigned g_histB[T_FRAMES][4096];
__device__ int4     g_sel[T_FRAMES];          // {Lg, Hg, Lb, Hb}
__device__ unsigned g_cntG[T_FRAMES];
__device__ unsigned g_cntB[T_FRAMES];
__device__ unsigned g_aux[T_FRAMES][2];       // [0]=count(kg>=HgB), [1]=count(kb<LbB)
__device__ unsigned g_h16[T_FRAMES][2][16];   // exact per-bin counts inside bracket
__device__ unsigned g_thr[T_FRAMES][2];       // {thrG_eff (gm2 key), thrB (|f| key)}
__device__ double   g_acc[T_FRAMES][4];       // cnt, sum(gm), sum(gm*x), sum(gm*y)
// SoA candidate buffers (16B-aligned rows for uint4 scans)
__device__ __align__(16) unsigned g_keyG[T_FRAMES][CAP];    // gm2 key
__device__ __align__(16) unsigned g_othG[T_FRAMES][CAP];    // |f| key
__device__ __align__(16) unsigned g_xyG [T_FRAMES][CAP];
__device__ __align__(16) unsigned g_keyB[T_FRAMES][CAP];    // |f| key
__device__ __align__(16) unsigned g_othB[T_FRAMES][CAP];    // gm2 key
__device__ __align__(16) unsigned g_xyB [T_FRAMES][CAP];

// ---------------- K0: zero scratch --------------------------------------------
__global__ void k_zero() {
    int i = blockIdx.x * blockDim.x + threadIdx.x;
    if (i < T_FRAMES * 4096) {
        ((unsigned*)g_histG)[i] = 0;
        ((unsigned*)g_histB)[i] = 0;
    }
    if (i < T_FRAMES * 32) ((unsigned*)g_h16)[i] = 0;
    if (i < T_FRAMES) {
        g_cntG[i] = 0; g_cntB[i] = 0;
        g_aux[i][0] = 0; g_aux[i][1] = 0;
        g_acc[i][0] = 0.0; g_acc[i][1] = 0.0; g_acc[i][2] = 0.0; g_acc[i][3] = 0.0;
    }
}

// ------ K1: SAMPLED top-12-bit histograms; G replicated by lane parity ---------
// Atomic-throughput-bound (linear in samples, measured). Replicating the G
// histogram by lane parity halves its intra-warp same-bin replay degree.
// 2*4096 + 4096 words = 48KB static smem (single phase, no reload overhead).
__global__ void __launch_bounds__(TPB) k_shist(const float* __restrict__ frames) {
    __shared__ unsigned hG[2][4096];
    __shared__ unsigned hB[4096];
    for (int i = threadIdx.x; i < 8192; i += TPB) ((unsigned*)hG)[i] = 0;
    for (int i = threadIdx.x; i < 4096; i += TPB) hB[i] = 0;
    __syncthreads();

    const int t = blockIdx.y;
    const float* __restrict__ f = frames + (size_t)t * NPIX;
    const int x0 = threadIdx.x * 4;
    const int lane = threadIdx.x & 31;
    const int rep = lane & 1;
    const bool notLast = (threadIdx.x < TPB - 1);

    for (int s = 0; s < SH_ROWS; s++) {
        const int y = (blockIdx.x * SH_ROWS + s) * SAMPLE_STRIDE;   // <= 1016
        const int p = y * W_DIM + x0;
        float4 a = *(const float4*)(f + p);
        float4 b = *(const float4*)(f + p + W_DIM);   // y+1 valid
        float nx = __shfl_down_sync(FULLMASK, a.x, 1);
        if (lane == 31) nx = notLast ? f[p + 4] : 0.0f;

        float av[4] = {a.x, a.y, a.z, a.w};
        float bv[4] = {b.x, b.y, b.z, b.w};
        #pragma unroll
        for (int j = 0; j < 4; j++) {
            float gx = (j < 3) ? __fadd_rn(av[j + 1], -av[j])
                               : (notLast ? __fadd_rn(nx, -av[3]) : 0.0f);
            float gy = __fadd_rn(bv[j], -av[j]);
            float gm2 = __fadd_rn(__fmul_rn(gx, gx), __fmul_rn(gy, gy));
            atomicAdd(&hG[rep][__float_as_uint(gm2) >> 20], 1u);
            atomicAdd(&hB[__float_as_uint(fabsf(av[j])) >> 20], 1u);
        }
    }
    __syncthreads();
    for (int i = threadIdx.x; i < 4096; i += TPB) {
        unsigned v = hG[0][i] + hG[1][i];
        if (v) atomicAdd(&g_histG[t][i], v);
        v = hB[i];
        if (v) atomicAdd(&g_histB[t][i], v);
    }
}

// ------------- "which bin holds rank K" (256 workers, blockDim>=256) ------------
template <int NBINS>
__device__ __forceinline__ void kth_bin(unsigned* h, unsigned K, unsigned* toff,
                                        int* s_bin, unsigned* s_rem) {
    const int seg = NBINS / 256;
    const int tid = threadIdx.x;
    const bool act = (tid < 256);
    if (tid == 0) { *s_bin = 0; *s_rem = 0; }
    unsigned s = 0;
    const int base = tid * seg;
    if (act) {
        #pragma unroll
        for (int i = 0; i < seg; i++) s += h[base + i];
        toff[tid] = s;
    }
    __syncthreads();
    if (tid == 0) {
        unsigned run = 0;
        for (int i = 0; i < 256; i++) { unsigned v = toff[i]; toff[i] = run; run += v; }
    }
    __syncthreads();
    if (act) {
        unsigned off = toff[tid];
        if (K >= off && K < off + s) {
            unsigned run = off;
            for (int i = 0; i < seg; i++) {
                unsigned c = h[base + i];
                if (K < run + c) { *s_bin = base + i; *s_rem = K - run; break; }
                run += c;
            }
        }
    }
    __syncthreads();
}

// ---------------- K2: bracket bins from sample histogram ------------------------
__global__ void __launch_bounds__(TPB) k_bracket() {
    __shared__ unsigned h[4096];
    __shared__ unsigned toff[256];
    __shared__ int s_bin;
    __shared__ unsigned s_rem;
    const int t = blockIdx.x;
    const double nm1 = (double)(NSAMP - 1);
    for (int which = 0; which < 2; which++) {
        const unsigned* src = which ? g_histB[t] : g_histG[t];
        const double q = which ? QB : QG;
        for (int i = threadIdx.x; i < 4096; i += TPB) h[i] = src[i];
        __syncthreads();
        unsigned klo = (unsigned)((q - DMARG) * nm1);
        unsigned khi = (unsigned)((q + DMARG) * nm1) + 1u;
        if (khi > (unsigned)(NSAMP - 1)) khi = (unsigned)(NSAMP - 1);
        kth_bin<4096>(h, klo, toff, &s_bin, &s_rem);
        int L0 = s_bin;
        __syncthreads();
        kth_bin<4096>(h, khi, toff, &s_bin, &s_rem);
        int H0 = s_bin;
        if (threadIdx.x == 0) {
            int L = L0;
            int H = H0;
            if (H > L + 15) H = L + 15;      // mini-hist width cap
            if (H < L) H = L;
            if (which == 0) { g_sel[t].x = L; g_sel[t].y = H; }
            else            { g_sel[t].z = L; g_sel[t].w = H; }
        }
        __syncthreads();
    }
}

// ------------- cold path: staging overflow -> direct global append --------------
__device__ __noinline__ void overflow_push(int t, bool inG, bool inB,
                                           unsigned kg, unsigned kb, unsigned xy,
                                           int Lg, int Lb) {
    if (inG) {
        unsigned g = atomicAdd(&g_cntG[t], 1u);
        if (g < CAP) { g_keyG[t][g] = kg; g_othG[t][g] = kb; g_xyG[t][g] = xy; }
        atomicAdd(&g_h16[t][0][(kg >> 20) - (unsigned)Lg], 1u);
    }
    if (inB) {
        unsigned g = atomicAdd(&g_cntB[t], 1u);
        if (g < CAP) { g_keyB[t][g] = kb; g_othB[t][g] = kg; g_xyB[t][g] = xy; }
        atomicAdd(&g_h16[t][1][(kb >> 20) - (unsigned)Lb], 1u);
    }
}

struct Acc { int cnt, nA, nBB; float sgA0, sgA1, sgA2, sgA3, sgy; };

// -------- hot row body: consumes preloaded a (this row) and b (row below) -------
template <bool HB>
__device__ __forceinline__ void row_body(
    const float* __restrict__ f, int t, int y, int x0, int lane, bool notLast,
    unsigned LgB, unsigned HgB, unsigned LbB, unsigned HbB, int Lg, int Lb,
    const float4& a, const float4& b, Acc& ac,
    unsigned* stK1, unsigned* stK2, unsigned* stX, unsigned* s_cnt)
{
    float nx = __shfl_down_sync(FULLMASK, a.x, 1);
    if (lane == 31) nx = notLast ? f[y * W_DIM + x0 + 4] : 0.0f;
    const float yf = (float)y;
    const unsigned xyb = (unsigned)((y << 10) | x0);
    float av[4] = {a.x, a.y, a.z, a.w};
    float bv[4] = {b.x, b.y, b.z, b.w};
    #pragma unroll
    for (int j = 0; j < 4; j++) {
        float gx = (j < 3) ? __fadd_rn(av[j + 1], -av[j])
                           : (notLast ? __fadd_rn(nx, -av[3]) : 0.0f);
        float gm2;
        if (HB) {
            float gy = __fadd_rn(bv[j], -av[j]);
            gm2 = __fadd_rn(__fmul_rn(gx, gx), __fmul_rn(gy, gy));
        } else {
            gm2 = __fadd_rn(__fmul_rn(gx, gx), 0.0f);
        }
        unsigned kg = __float_as_uint(gm2);
        unsigned kb = __float_as_uint(fabsf(av[j]));
        bool aboveG = (kg >= HgB);
        bool belowB = (kb < LbB);
        ac.nA  += aboveG;
        ac.nBB += belowB;
        // branchless definite-masked accumulation (approx sqrt: 1 MUFU)
        float gm;
        asm("sqrt.approx.f32 %0, %1;" : "=f"(gm) : "f"(gm2));
        bool def = aboveG & belowB;
        float w = def ? gm : 0.0f;
        ac.cnt += def;
        if (j == 0) ac.sgA0 += w;
        if (j == 1) ac.sgA1 += w;
        if (j == 2) ac.sgA2 += w;
        if (j == 3) ac.sgA3 += w;
        ac.sgy += w * yf;
        bool inG = (kg >= LgB) & !aboveG;
        bool inB = !belowB & (kb < HbB);
        if (inG | inB) {
            unsigned fl = (inG ? 0x80000000u : 0u) | (inB ? 0x40000000u : 0u);
            unsigned idx = atomicAdd(s_cnt, 1u);
            if (idx < STCAP) {
                stK1[idx] = kg; stK2[idx] = kb; stX[idx] = (xyb | (unsigned)j) | fl;
            } else {
                overflow_push(t, inG, inB, kg, kb, xyb | (unsigned)j, Lg, Lb);
            }
        }
    }
}

// ------- K3: single full pass: counts + definite sums + compaction --------------
// Software-pipelined rows: prefetch row y+2 while computing row y.
__global__ void __launch_bounds__(TPB) k_main(const float* __restrict__ frames) {
    __shared__ unsigned stK1[STCAP], stK2[STCAP], stX[STCAP];
    __shared__ unsigned s_cnt;
    __shared__ unsigned h16G[16], h16B[16];
    if (threadIdx.x == 0) s_cnt = 0;
    if (threadIdx.x < 16) { h16G[threadIdx.x] = 0; h16B[threadIdx.x] = 0; }
    __syncthreads();

    const int t = blockIdx.y;
    const int4 sel = g_sel[t];
    const int Lg = sel.x, Hg = sel.y, Lb = sel.z, Hb = sel.w;
    const unsigned LgB = (unsigned)Lg << 20;
    const unsigned HgB = (Hg >= 4095) ? 0xFFFFFFFFu : ((unsigned)(Hg + 1) << 20);
    const unsigned LbB = (unsigned)Lb << 20;
    const unsigned HbB = (Hb >= 4095) ? 0xFFFFFFFFu : ((unsigned)(Hb + 1) << 20);
    const float* __restrict__ f = frames + (size_t)t * NPIX;
    const int row0 = blockIdx.x * MROWS;
    const int x0 = threadIdx.x * 4;
    const int lane = threadIdx.x & 31;
    const bool notLast = (threadIdx.x < TPB - 1);

    Acc ac = {0, 0, 0, 0.f, 0.f, 0.f, 0.f, 0.f};
    float4 a = *(const float4*)(f + row0 * W_DIM + x0);          // row y
    float4 b = *(const float4*)(f + (row0 + 1) * W_DIM + x0);    // row y+1

    if (row0 + MROWS < H_DIM) {
        #pragma unroll 1
        for (int r = 0; r < MROWS; r++) {
            const int y = row0 + r;
            float4 bn = *(const float4*)(f + (y + 2) * W_DIM + x0);   // prefetch
            row_body<true>(f, t, y, x0, lane, notLast,
                           LgB, HgB, LbB, HbB, Lg, Lb, a, b, ac,
                           stK1, stK2, stX, &s_cnt);
            a = b; b = bn;
        }
    } else {
        #pragma unroll 1
        for (int r = 0; r < MROWS - 1; r++) {
            const int y = row0 + r;
            float4 bn = (y + 2 <= H_DIM - 1)
                        ? *(const float4*)(f + (y + 2) * W_DIM + x0)
                        : make_float4(0.f, 0.f, 0.f, 0.f);
            row_body<true>(f, t, y, x0, lane, notLast,
                           LgB, HgB, LbB, HbB, Lg, Lb, a, b, ac,
                           stK1, stK2, stX, &s_cnt);
            a = b; b = bn;
        }
        row_body<false>(f, t, H_DIM - 1, x0, lane, notLast,
                        LgB, HgB, LbB, HbB, Lg, Lb, a, b, ac,
                        stK1, stK2, stX, &s_cnt);
    }

    // ---- flush staged candidates: mini-hist + warp-aggregated global append ----
    __syncthreads();
    unsigned n = s_cnt; if (n > STCAP) n = STCAP;
    for (unsigned base = 0; base < n; base += TPB) {
        unsigned i = base + threadIdx.x;
        bool act = (i < n);
        unsigned k1 = 0, k2 = 0, x = 0;
        bool inG = false, inB = false;
        if (act) {
            k1 = stK1[i]; k2 = stK2[i]; x = stX[i];
            inG = (x >> 31) != 0; inB = ((x >> 30) & 1u) != 0;
            x &= 0xFFFFFu;
        }
        if (act && inG) atomicAdd(&h16G[(k1 >> 20) - (unsigned)Lg], 1u);
        if (act && inB) atomicAdd(&h16B[(k2 >> 20) - (unsigned)Lb], 1u);

        unsigned m = __ballot_sync(FULLMASK, act && inG);
        if (m) {
            int leader = __ffs(m) - 1;
            unsigned bp = 0;
            if (lane == leader) bp = atomicAdd(&g_cntG[t], (unsigned)__popc(m));
            bp = __shfl_sync(FULLMASK, bp, leader);
            if (act && inG) {
                unsigned d = bp + (unsigned)__popc(m & ((1u << lane) - 1u));
                if (d < CAP) { g_keyG[t][d] = k1; g_othG[t][d] = k2; g_xyG[t][d] = x; }
            }
        }
        m = __ballot_sync(FULLMASK, act && inB);
        if (m) {
            int leader = __ffs(m) - 1;
            unsigned bp = 0;
            if (lane == leader) bp = atomicAdd(&g_cntB[t], (unsigned)__popc(m));
            bp = __shfl_sync(FULLMASK, bp, leader);
            if (act && inB) {
                unsigned d = bp + (unsigned)__popc(m & ((1u << lane) - 1u));
                if (d < CAP) { g_keyB[t][d] = k2; g_othB[t][d] = k1; g_xyB[t][d] = x; }
            }
        }
    }
    __syncthreads();
    if (threadIdx.x < 16) {
        unsigned v = h16G[threadIdx.x];
        if (v) atomicAdd(&g_h16[t][0][threadIdx.x], v);
        v = h16B[threadIdx.x];
        if (v) atomicAdd(&g_h16[t][1][threadIdx.x], v);
    }

    // ---- reconstruct sums, warp reduce, one atomic set per warp ----
    int cnt = ac.cnt, nA = ac.nA, nBB = ac.nBB;
    float sg  = ((ac.sgA0 + ac.sgA1) + (ac.sgA2 + ac.sgA3));
    float sgx = (float)x0 * sg + (ac.sgA1 + 2.0f * ac.sgA2 + 3.0f * ac.sgA3);
    float sgy = ac.sgy;
    #pragma unroll
    for (int o = 16; o; o >>= 1) {
        cnt += __shfl_down_sync(FULLMASK, cnt, o);
        nA  += __shfl_down_sync(FULLMASK, nA,  o);
        nBB += __shfl_down_sync(FULLMASK, nBB, o);
        sg  += __shfl_down_sync(FULLMASK, sg,  o);
        sgx += __shfl_down_sync(FULLMASK, sgx, o);
        sgy += __shfl_down_sync(FULLMASK, sgy, o);
    }
    if (lane == 0) {
        atomicAdd(&g_aux[t][0], (unsigned)nA);
        atomicAdd(&g_aux[t][1], (unsigned)nBB);
        atomicAdd(&g_acc[t][0], (double)cnt);
        atomicAdd(&g_acc[t][1], (double)sg);
        atomicAdd(&g_acc[t][2], (double)sgx);
        atomicAdd(&g_acc[t][3], (double)sgy);
    }
}

// ------- K4a: exact thresholds (2 vectorized buffer passes, 1024 threads) -------
__global__ void __launch_bounds__(TPB_T) k_thresh() {
    __shared__ unsigned h[4096];
    __shared__ unsigned toff[256];
    __shared__ int s_bin;
    __shared__ unsigned s_rem;
    __shared__ int sh_b1;
    __shared__ unsigned sh_r1;
    const int t = blockIdx.x;
    const int w = blockIdx.y;                 // 0 = G(gm2), 1 = B(|f|)
    const unsigned* __restrict__ key = w ? g_keyB[t] : g_keyG[t];
    const unsigned cnt = min(w ? g_cntB[t] : g_cntG[t], (unsigned)CAP);
    const int L = w ? g_sel[t].z : g_sel[t].x;
    const int tid = threadIdx.x;

    if (tid == 0) {
        long long below;
        if (w == 0) {
            // belowG = NPIX - inG_exact - aboveG_exact
            below = (long long)NPIX - (long long)g_cntG[t] - (long long)g_aux[t][0];
        } else {
            below = (long long)g_aux[t][1];
        }
        long long r = (long long)(w ? KB_RANK : KG_RANK) - below;
        if (r < 0) r = 0;
        if (r > (long long)cnt - 1) r = (long long)cnt - 1;
        unsigned run = 0; int b1 = L; unsigned r1 = (unsigned)r;
        for (int i = 0; i < 16; i++) {
            unsigned c = g_h16[t][w][i];
            if ((unsigned)r < run + c) { b1 = L + i; r1 = (unsigned)r - run; break; }
            run += c;
        }
        sh_b1 = b1; sh_r1 = r1;
    }
    __syncthreads();
    const unsigned b1 = (unsigned)sh_b1;
    const unsigned r1 = sh_r1;

    const unsigned nv4 = cnt >> 2;
    const unsigned tail = nv4 << 2;
    const uint4* __restrict__ key4 = (const uint4*)key;

    // level 1: bits 8..19 within bin b1
    for (int i = tid; i < 4096; i += TPB_T) h[i] = 0;
    __syncthreads();
    for (unsigned u = tid; u < nv4; u += TPB_T) {
        uint4 k4 = key4[u];
        if ((k4.x >> 20) == b1) atomicAdd(&h[(k4.x >> 8) & 0xFFFu], 1u);
        if ((k4.y >> 20) == b1) atomicAdd(&h[(k4.y >> 8) & 0xFFFu], 1u);
        if ((k4.z >> 20) == b1) atomicAdd(&h[(k4.z >> 8) & 0xFFFu], 1u);
        if ((k4.w >> 20) == b1) atomicAdd(&h[(k4.w >> 8) & 0xFFFu], 1u);
    }
    if ((unsigned)tid < cnt - tail) {
        unsigned k = key[tail + tid];
        if ((k >> 20) == b1) atomicAdd(&h[(k >> 8) & 0xFFFu], 1u);
    }
    __syncthreads();
    kth_bin<4096>(h, r1, toff, &s_bin, &s_rem);
    int b2 = s_bin; unsigned r2 = s_rem;
    __syncthreads();
    // level 2: low 8 bits
    for (int i = tid; i < 256; i += TPB_T) h[i] = 0;
    __syncthreads();
    unsigned pref = (b1 << 12) | (unsigned)b2;
    for (unsigned u = tid; u < nv4; u += TPB_T) {
        uint4 k4 = key4[u];
        if ((k4.x >> 8) == pref) atomicAdd(&h[k4.x & 0xFFu], 1u);
        if ((k4.y >> 8) == pref) atomicAdd(&h[k4.y & 0xFFu], 1u);
        if ((k4.z >> 8) == pref) atomicAdd(&h[k4.z & 0xFFu], 1u);
        if ((k4.w >> 8) == pref) atomicAdd(&h[k4.w & 0xFFu], 1u);
    }
    if ((unsigned)tid < cnt - tail) {
        unsigned k = key[tail + tid];
        if ((k >> 8) == pref) atomicAdd(&h[k & 0xFFu], 1u);
    }
    __syncthreads();
    kth_bin<256>(h, r2, toff, &s_bin, &s_rem);
    unsigned thr = (pref << 8) | (unsigned)s_bin;
    if (tid == 0) {
        if (w == 0) {
            // widen: reference mask is sqrtf(gm2) > sqrtf(thr2)
            float s = __fsqrt_rn(__uint_as_float(thr));
            unsigned k = thr;
            for (int i = 0; i < 64; i++) {
                if (__fsqrt_rn(__uint_as_float(k + 1u)) == s) k++;
                else break;
            }
            g_thr[t][0] = k;
        } else {
            g_thr[t][1] = thr;
        }
    }
}

// ---------------- K4b: resolve ambiguous pixels exactly (vectorized) ------------
__global__ void __launch_bounds__(TPB) k_apply() {
    const int t = blockIdx.x;
    const int q = blockIdx.y;            // NSLICE slices per frame
    const unsigned thrG = g_thr[t][0];
    const unsigned thrB = g_thr[t][1];
    const unsigned Hg = (unsigned)g_sel[t].y;
    const unsigned cG = min(g_cntG[t], (unsigned)CAP);
    const unsigned cB = min(g_cntB[t], (unsigned)CAP);

    int   cnt = 0;
    float sg = 0.f, sgx = 0.f, sgy = 0.f;

    // --- G side ---
    {
        const uint4* __restrict__ k4p = (const uint4*)g_keyG[t];
        const uint4* __restrict__ o4p = (const uint4*)g_othG[t];
        const unsigned nv4 = cG >> 2, tail = nv4 << 2;
        for (unsigned u = q * TPB + threadIdx.x; u < nv4; u += TPB * NSLICE) {
            uint4 k4 = k4p[u];
            uint4 o4 = o4p[u];
            unsigned kk[4] = {k4.x, k4.y, k4.z, k4.w};
            unsigned oo[4] = {o4.x, o4.y, o4.z, o4.w};
            #pragma unroll
            for (int j = 0; j < 4; j++) {
                if (kk[j] > thrG && oo[j] < thrB) {
                    unsigned xy = g_xyG[t][u * 4 + j];
                    float gm = __fsqrt_rn(__uint_as_float(kk[j]));
                    cnt++;
                    sg  += gm;
                    sgx += gm * (float)(xy & 1023u);
                    sgy += gm * (float)(xy >> 10);
                }
            }
        }
        if (q == 0 && (unsigned)threadIdx.x < cG - tail) {
            unsigned i = tail + threadIdx.x;
            unsigned k = g_keyG[t][i], o = g_othG[t][i];
            if (k > thrG && o < thrB) {
                unsigned xy = g_xyG[t][i];
                float gm = __fsqrt_rn(__uint_as_float(k));
                cnt++;
                sg  += gm;
                sgx += gm * (float)(xy & 1023u);
                sgy += gm * (float)(xy >> 10);
            }
        }
    }
    // --- B side (only pixels with gbin strictly above the G bracket) ---
    {
        const uint4* __restrict__ k4p = (const uint4*)g_keyB[t];
        const uint4* __restrict__ o4p = (const uint4*)g_othB[t];
        const unsigned nv4 = cB >> 2, tail = nv4 << 2;
        for (unsigned u = q * TPB + threadIdx.x; u < nv4; u += TPB * NSLICE) {
            uint4 k4 = k4p[u];
            uint4 o4 = o4p[u];
            unsigned kk[4] = {k4.x, k4.y, k4.z, k4.w};
            unsigned oo[4] = {o4.x, o4.y, o4.z, o4.w};
            #pragma unroll
            for (int j = 0; j < 4; j++) {
                if ((oo[j] >> 20) > Hg && oo[j] > thrG && kk[j] < thrB) {
                    unsigned xy = g_xyB[t][u * 4 + j];
                    float gm = __fsqrt_rn(__uint_as_float(oo[j]));
                    cnt++;
                    sg  += gm;
                    sgx += gm * (float)(xy & 1023u);
                    sgy += gm * (float)(xy >> 10);
                }
            }
        }
        if (q == 0 && (unsigned)threadIdx.x < cB - tail) {
            unsigned i = tail + threadIdx.x;
            unsigned k = g_keyB[t][i], o = g_othB[t][i];
            if ((o >> 20) > Hg && o > thrG && k < thrB) {
                unsigned xy = g_xyB[t][i];
                float gm = __fsqrt_rn(__uint_as_float(o));
                cnt++;
                sg  += gm;
                sgx += gm * (float)(xy & 1023u);
                sgy += gm * (float)(xy >> 10);
            }
        }
    }
    #pragma unroll
    for (int o = 16; o; o >>= 1) {
        cnt += __shfl_down_sync(FULLMASK, cnt, o);
        sg  += __shfl_down_sync(FULLMASK, sg,  o);
        sgx += __shfl_down_sync(FULLMASK, sgx, o);
        sgy += __shfl_down_sync(FULLMASK, sgy, o);
    }
    if ((threadIdx.x & 31) == 0) {
        atomicAdd(&g_acc[t][0], (double)cnt);
        atomicAdd(&g_acc[t][1], (double)sg);
        atomicAdd(&g_acc[t][2], (double)sgx);
        atomicAdd(&g_acc[t][3], (double)sgy);
    }
}

// ------------- block reduction over 64 doubles (64 threads) ---------------------
__device__ __forceinline__ double bred64(double v, double* red) {
    int t = threadIdx.x;
    red[t] = v;
    __syncthreads();
    for (int s = 32; s > 0; s >>= 1) {
        if (t < s) red[t] += red[t + s];
        __syncthreads();
    }
    double r = red[0];
    __syncthreads();
    return r;
}

// ---------------- K5: depthwise conv + final 8 stats (64 threads) ---------------
__global__ void k_final(const float* __restrict__ conv_w,
                        const float* __restrict__ conv_b,
                        float* __restrict__ out) {
    __shared__ double sst[4][T_FRAMES];
    __shared__ double sy[4][T_FRAMES];
    __shared__ double red[T_FRAMES];
    const int t = threadIdx.x;   // 64 threads
    const int n = T_FRAMES;
    {
        double c = g_acc[t][0], sg = g_acc[t][1], sgx = g_acc[t][2], sgy = g_acc[t][3];
        double pil = c < 1e-6 ? 1e-6 : c;
        double ws  = sg < 1e-6 ? 1e-6 : sg;
        sst[0][t] = c / (double)NPIX;
        sst[1][t] = sg / pil;
        sst[2][t] = sgx / ws / (double)W_DIM;
        sst[3][t] = sgy / ws / (double)H_DIM;
    }
    __syncthreads();
    #pragma unroll
    for (int c = 0; c < 4; c++) {
        double v = (double)conv_b[c] + (double)conv_w[c * 3 + 1] * sst[c][t];
        if (t > 0)     v += (double)conv_w[c * 3 + 0] * sst[c][t - 1];
        if (t < n - 1) v += (double)conv_w[c * 3 + 2] * sst[c][t + 1];
        sy[c][t] = v;
    }
    __syncthreads();

    double lm = bred64(sy[0][t], red) / n;
    double im = bred64(sy[1][t], red) / n;
    double tn = (double)t / (double)(n - 1) - 0.5;
    double lt  = bred64((sy[0][t] - lm) * tn, red) * 6.0 / n;
    double itr = bred64((sy[1][t] - im) * tn, red) * 6.0 / n;

    double dx = 0.0, dy = 0.0, sp = 0.0;
    if (t < n - 1) {
        dx = sy[2][t + 1] - sy[2][t];
        dy = sy[3][t + 1] - sy[3][t];
        sp = sqrt(dx * dx + dy * dy);
    }
    double sdx  = bred64(dx, red);
    double sdy  = bred64(dy, red);
    double ssum = bred64(sp, red);
    double ms = ssum / (double)(n - 1);
    double var = bred64(t < n - 1 ? (sp - ms) * (sp - ms) : 0.0, red) / (double)(n - 2);

    if (t == 0) {
        out[0] = (float)lm;
        out[1] = (float)lt;
        out[2] = (float)im;
        out[3] = (float)itr;
        out[4] = (float)ms;
        out[5] = (float)(atan2(sdy, sdx) / 3.14159265358979323846);
        out[6] = (float)((sy[0][n - 1] - sy[0][0]) / (double)(n - 1));
        out[7] = (float)sqrt(var);
    }
}

// ---------------- entry point -----------------------------------------------------
extern "C" void kernel_launch(void* const* d_in, const int* in_sizes, int n_in,
                              void* d_out, int out_size) {
    const float* frames = (const float*)d_in[0];
    // d_in[1] = observed_mask (unused by reference)
    const float* conv_w = (const float*)d_in[2];
    const float* conv_b = (const float*)d_in[3];
    float* out = (float*)d_out;

    k_zero<<<(T_FRAMES * 4096 + TPB - 1) / TPB, TPB>>>();
    k_shist<<<dim3(SH_BLOCKS, T_FRAMES), TPB>>>(frames);
    k_bracket<<<T_FRAMES, TPB>>>();
    k_main<<<dim3(MCHUNKS, T_FRAMES), TPB>>>(frames);
    k_thresh<<<dim3(T_FRAMES, 2), TPB_T>>>();
    k_apply<<<dim3(T_FRAMES, NSLICE), TPB>>>();
    k_final<<<1, T_FRAMES>>>(conv_w, conv_b, out);
}

// round 17
// speedup vs baseline: 1.0435x; 1.0212x over previous
#include <cuda_runtime.h>
#include <stdint.h>
#include <math.h>

#define T_FRAMES 64
#define H_DIM 1024
#define W_DIM 1024
#define NPIX (H_DIM * W_DIM)
#define TPB 256
#define TPB_T 1024
#define FULLMASK 0xffffffffu

// sampling pass
#define SAMPLE_STRIDE 8
#define NSROWS (H_DIM / SAMPLE_STRIDE)      // 128 sample rows/frame
#define NSAMP (NSROWS * W_DIM)              // 131072 samples/frame
#define SH_BLOCKS 16
#define SH_ROWS (NSROWS / SH_BLOCKS)        // 8 sample rows per block

// main pass
#define MROWS 16
#define MCHUNKS (H_DIM / MROWS)             // 64 blocks per frame

#define CAP 65536
#define STCAP 2048
#define NSLICE 16

// population ranks (0-based), matching Python int() truncation
#define KG_RANK 891288u   // int(0.85*(NPIX-1))
#define KB_RANK 314572u   // int(0.30*(NPIX-1))
#define QG 0.85
#define QB 0.30
#define DMARG 0.005       // ~5 sigma of sampling error at NSAMP=131072

// ---------------- device scratch ----------------
// g_hist*: zero at load (static init); k_bracket re-zeroes its frame's rows
// AFTER reading them, so every invocation/replay sees clean histograms.
__device__ unsigned g_histG[T_FRAMES][4096];
__device__ unsigned g_histB[T_FRAMES][4096];
__device__ int4     g_sel[T_FRAMES];          // {Lg, Hg, Lb, Hb}
__device__ unsigned g_cntG[T_FRAMES];
__device__ unsigned g_cntB[T_FRAMES];
__device__ unsigned g_aux[T_FRAMES][2];       // [0]=count(kg>=HgB), [1]=count(kb<LbB)
__device__ unsigned g_h16[T_FRAMES][2][16];   // exact per-bin counts inside bracket
__device__ unsigned g_thr[T_FRAMES][2];       // {thrG_eff (gm2 key), thrB (|f| key)}
__device__ double   g_acc[T_FRAMES][4];       // cnt, sum(gm), sum(gm*x), sum(gm*y)
// SoA candidate buffers (16B-aligned rows for uint4 scans)
__device__ __align__(16) unsigned g_keyG[T_FRAMES][CAP];    // gm2 key
__device__ __align__(16) unsigned g_othG[T_FRAMES][CAP];    // |f| key
__device__ __align__(16) unsigned g_xyG [T_FRAMES][CAP];
__device__ __align__(16) unsigned g_keyB[T_FRAMES][CAP];    // |f| key
__device__ __align__(16) unsigned g_othB[T_FRAMES][CAP];    // gm2 key
__device__ __align__(16) unsigned g_xyB [T_FRAMES][CAP];

// ------ K1: SAMPLED top-12-bit histograms; G replicated by lane parity ---------
__global__ void __launch_bounds__(TPB) k_shist(const float* __restrict__ frames) {
    __shared__ unsigned hG[2][4096];
    __shared__ unsigned hB[4096];
    for (int i = threadIdx.x; i < 8192; i += TPB) ((unsigned*)hG)[i] = 0;
    for (int i = threadIdx.x; i < 4096; i += TPB) hB[i] = 0;
    __syncthreads();

    const int t = blockIdx.y;
    const float* __restrict__ f = frames + (size_t)t * NPIX;
    const int x0 = threadIdx.x * 4;
    const int lane = threadIdx.x & 31;
    const int rep = lane & 1;
    const bool notLast = (threadIdx.x < TPB - 1);

    for (int s = 0; s < SH_ROWS; s++) {
        const int y = (blockIdx.x * SH_ROWS + s) * SAMPLE_STRIDE;   // <= 1016
        const int p = y * W_DIM + x0;
        float4 a = *(const float4*)(f + p);
        float4 b = *(const float4*)(f + p + W_DIM);   // y+1 valid
        float nx = __shfl_down_sync(FULLMASK, a.x, 1);
        if (lane == 31) nx = notLast ? f[p + 4] : 0.0f;

        float av[4] = {a.x, a.y, a.z, a.w};
        float bv[4] = {b.x, b.y, b.z, b.w};
        #pragma unroll
        for (int j = 0; j < 4; j++) {
            float gx = (j < 3) ? __fadd_rn(av[j + 1], -av[j])
                               : (notLast ? __fadd_rn(nx, -av[3]) : 0.0f);
            float gy = __fadd_rn(bv[j], -av[j]);
            float gm2 = __fadd_rn(__fmul_rn(gx, gx), __fmul_rn(gy, gy));
            atomicAdd(&hG[rep][__float_as_uint(gm2) >> 20], 1u);
            atomicAdd(&hB[__float_as_uint(fabsf(av[j])) >> 20], 1u);
        }
    }
    __syncthreads();
    for (int i = threadIdx.x; i < 4096; i += TPB) {
        unsigned v = hG[0][i] + hG[1][i];
        if (v) atomicAdd(&g_histG[t][i], v);
        v = hB[i];
        if (v) atomicAdd(&g_histB[t][i], v);
    }
}

// ------------- "which bin holds rank K" (256 workers, blockDim>=256) ------------
template <int NBINS>
__device__ __forceinline__ void kth_bin(unsigned* h, unsigned K, unsigned* toff,
                                        int* s_bin, unsigned* s_rem) {
    const int seg = NBINS / 256;
    const int tid = threadIdx.x;
    const bool act = (tid < 256);
    if (tid == 0) { *s_bin = 0; *s_rem = 0; }
    unsigned s = 0;
    const int base = tid * seg;
    if (act) {
        #pragma unroll
        for (int i = 0; i < seg; i++) s += h[base + i];
        toff[tid] = s;
    }
    __syncthreads();
    if (tid == 0) {
        unsigned run = 0;
        for (int i = 0; i < 256; i++) { unsigned v = toff[i]; toff[i] = run; run += v; }
    }
    __syncthreads();
    if (act) {
        unsigned off = toff[tid];
        if (K >= off && K < off + s) {
            unsigned run = off;
            for (int i = 0; i < seg; i++) {
                unsigned c = h[base + i];
                if (K < run + c) { *s_bin = base + i; *s_rem = K - run; break; }
                run += c;
            }
        }
    }
    __syncthreads();
}

// ------- K2: bracket bins; zeroes per-frame counters + re-zeroes histograms -----
__global__ void __launch_bounds__(TPB) k_bracket() {
    __shared__ unsigned h[4096];
    __shared__ unsigned toff[256];
    __shared__ int s_bin;
    __shared__ unsigned s_rem;
    const int t = blockIdx.x;
    // zero this frame's counters (runs before k_main by kernel ordering)
    if (threadIdx.x < 16) { g_h16[t][0][threadIdx.x] = 0; g_h16[t][1][threadIdx.x] = 0; }
    if (threadIdx.x == 16) {
        g_cntG[t] = 0; g_cntB[t] = 0;
        g_aux[t][0] = 0; g_aux[t][1] = 0;
        g_acc[t][0] = 0.0; g_acc[t][1] = 0.0; g_acc[t][2] = 0.0; g_acc[t][3] = 0.0;
    }
    const double nm1 = (double)(NSAMP - 1);
    for (int which = 0; which < 2; which++) {
        const unsigned* src = which ? g_histB[t] : g_histG[t];
        const double q = which ? QB : QG;
        for (int i = threadIdx.x; i < 4096; i += TPB) h[i] = src[i];
        __syncthreads();
        unsigned klo = (unsigned)((q - DMARG) * nm1);
        unsigned khi = (unsigned)((q + DMARG) * nm1) + 1u;
        if (khi > (unsigned)(NSAMP - 1)) khi = (unsigned)(NSAMP - 1);
        kth_bin<4096>(h, klo, toff, &s_bin, &s_rem);
        int L0 = s_bin;
        __syncthreads();
        kth_bin<4096>(h, khi, toff, &s_bin, &s_rem);
        int H0 = s_bin;
        if (threadIdx.x == 0) {
            int L = L0;
            int H = H0;
            if (H > L + 15) H = L + 15;      // mini-hist width cap
            if (H < L) H = L;
            if (which == 0) { g_sel[t].x = L; g_sel[t].y = H; }
            else            { g_sel[t].z = L; g_sel[t].w = H; }
        }
        __syncthreads();
    }
    // re-zero this frame's histograms for the next invocation (we own them)
    for (int i = threadIdx.x; i < 4096; i += TPB) {
        g_histG[t][i] = 0;
        g_histB[t][i] = 0;
    }
}

// ------------- cold path: staging overflow -> direct global append --------------
__device__ __noinline__ void overflow_push(int t, bool inG, bool inB,
                                           unsigned kg, unsigned kb, unsigned xy,
                                           int Lg, int Lb) {
    if (inG) {
        unsigned g = atomicAdd(&g_cntG[t], 1u);
        if (g < CAP) { g_keyG[t][g] = kg; g_othG[t][g] = kb; g_xyG[t][g] = xy; }
        atomicAdd(&g_h16[t][0][(kg >> 20) - (unsigned)Lg], 1u);
    }
    if (inB) {
        unsigned g = atomicAdd(&g_cntB[t], 1u);
        if (g < CAP) { g_keyB[t][g] = kb; g_othB[t][g] = kg; g_xyB[t][g] = xy; }
        atomicAdd(&g_h16[t][1][(kb >> 20) - (unsigned)Lb], 1u);
    }
}

struct Acc { int cnt, nA, nBB; float sgA0, sgA1, sgA2, sgA3, sgy; };

// -------- hot row body: consumes preloaded a (this row) and b (row below) -------
template <bool HB>
__device__ __forceinline__ void row_body(
    const float* __restrict__ f, int t, int y, int x0, int lane, bool notLast,
    unsigned LgB, unsigned HgB, unsigned LbB, unsigned HbB, int Lg, int Lb,
    const float4& a, const float4& b, Acc& ac,
    unsigned* stK1, unsigned* stK2, unsigned* stX, unsigned* s_cnt)
{
    float nx = __shfl_down_sync(FULLMASK, a.x, 1);
    if (lane == 31) nx = notLast ? f[y * W_DIM + x0 + 4] : 0.0f;
    const float yf = (float)y;
    const unsigned xyb = (unsigned)((y << 10) | x0);
    float av[4] = {a.x, a.y, a.z, a.w};
    float bv[4] = {b.x, b.y, b.z, b.w};
    #pragma unroll
    for (int j = 0; j < 4; j++) {
        float gx = (j < 3) ? __fadd_rn(av[j + 1], -av[j])
                           : (notLast ? __fadd_rn(nx, -av[3]) : 0.0f);
        float gm2;
        if (HB) {
            float gy = __fadd_rn(bv[j], -av[j]);
            gm2 = __fadd_rn(__fmul_rn(gx, gx), __fmul_rn(gy, gy));
        } else {
            gm2 = __fadd_rn(__fmul_rn(gx, gx), 0.0f);
        }
        unsigned kg = __float_as_uint(gm2);
        unsigned kb = __float_as_uint(fabsf(av[j]));
        bool aboveG = (kg >= HgB);
        bool belowB = (kb < LbB);
        ac.nA  += aboveG;
        ac.nBB += belowB;
        // branchless definite-masked accumulation (approx sqrt: 1 MUFU)
        float gm;
        asm("sqrt.approx.f32 %0, %1;" : "=f"(gm) : "f"(gm2));
        bool def = aboveG & belowB;
        float w = def ? gm : 0.0f;
        ac.cnt += def;
        if (j == 0) ac.sgA0 += w;
        if (j == 1) ac.sgA1 += w;
        if (j == 2) ac.sgA2 += w;
        if (j == 3) ac.sgA3 += w;
        ac.sgy += w * yf;
        bool inG = (kg >= LgB) & !aboveG;
        bool inB = !belowB & (kb < HbB);
        if (inG | inB) {
            unsigned fl = (inG ? 0x80000000u : 0u) | (inB ? 0x40000000u : 0u);
            unsigned idx = atomicAdd(s_cnt, 1u);
            if (idx < STCAP) {
                stK1[idx] = kg; stK2[idx] = kb; stX[idx] = (xyb | (unsigned)j) | fl;
            } else {
                overflow_push(t, inG, inB, kg, kb, xyb | (unsigned)j, Lg, Lb);
            }
        }
    }
}

// ------- K3: single full pass: counts + definite sums + compaction --------------
// Software-pipelined rows: prefetch row y+2 while computing row y.
__global__ void __launch_bounds__(TPB) k_main(const float* __restrict__ frames) {
    __shared__ unsigned stK1[STCAP], stK2[STCAP], stX[STCAP];
    __shared__ unsigned s_cnt;
    __shared__ unsigned h16G[16], h16B[16];
    if (threadIdx.x == 0) s_cnt = 0;
    if (threadIdx.x < 16) { h16G[threadIdx.x] = 0; h16B[threadIdx.x] = 0; }
    __syncthreads();

    const int t = blockIdx.y;
    const int4 sel = g_sel[t];
    const int Lg = sel.x, Hg = sel.y, Lb = sel.z, Hb = sel.w;
    const unsigned LgB = (unsigned)Lg << 20;
    const unsigned HgB = (Hg >= 4095) ? 0xFFFFFFFFu : ((unsigned)(Hg + 1) << 20);
    const unsigned LbB = (unsigned)Lb << 20;
    const unsigned HbB = (Hb >= 4095) ? 0xFFFFFFFFu : ((unsigned)(Hb + 1) << 20);
    const float* __restrict__ f = frames + (size_t)t * NPIX;
    const int row0 = blockIdx.x * MROWS;
    const int x0 = threadIdx.x * 4;
    const int lane = threadIdx.x & 31;
    const bool notLast = (threadIdx.x < TPB - 1);

    Acc ac = {0, 0, 0, 0.f, 0.f, 0.f, 0.f, 0.f};
    float4 a = *(const float4*)(f + row0 * W_DIM + x0);          // row y
    float4 b = *(const float4*)(f + (row0 + 1) * W_DIM + x0);    // row y+1

    if (row0 + MROWS < H_DIM) {
        #pragma unroll 1
        for (int r = 0; r < MROWS; r++) {
            const int y = row0 + r;
            float4 bn = *(const float4*)(f + (y + 2) * W_DIM + x0);   // prefetch
            row_body<true>(f, t, y, x0, lane, notLast,
                           LgB, HgB, LbB, HbB, Lg, Lb, a, b, ac,
                           stK1, stK2, stX, &s_cnt);
            a = b; b = bn;
        }
    } else {
        #pragma unroll 1
        for (int r = 0; r < MROWS - 1; r++) {
            const int y = row0 + r;
            float4 bn = (y + 2 <= H_DIM - 1)
                        ? *(const float4*)(f + (y + 2) * W_DIM + x0)
                        : make_float4(0.f, 0.f, 0.f, 0.f);
            row_body<true>(f, t, y, x0, lane, notLast,
                           LgB, HgB, LbB, HbB, Lg, Lb, a, b, ac,
                           stK1, stK2, stX, &s_cnt);
            a = b; b = bn;
        }
        row_body<false>(f, t, H_DIM - 1, x0, lane, notLast,
                        LgB, HgB, LbB, HbB, Lg, Lb, a, b, ac,
                        stK1, stK2, stX, &s_cnt);
    }

    // ---- flush staged candidates: mini-hist + warp-aggregated global append ----
    __syncthreads();
    unsigned n = s_cnt; if (n > STCAP) n = STCAP;
    for (unsigned base = 0; base < n; base += TPB) {
        unsigned i = base + threadIdx.x;
        bool act = (i < n);
        unsigned k1 = 0, k2 = 0, x = 0;
        bool inG = false, inB = false;
        if (act) {
            k1 = stK1[i]; k2 = stK2[i]; x = stX[i];
            inG = (x >> 31) != 0; inB = ((x >> 30) & 1u) != 0;
            x &= 0xFFFFFu;
        }
        if (act && inG) atomicAdd(&h16G[(k1 >> 20) - (unsigned)Lg], 1u);
        if (act && inB) atomicAdd(&h16B[(k2 >> 20) - (unsigned)Lb], 1u);

        unsigned m = __ballot_sync(FULLMASK, act && inG);
        if (m) {
            int leader = __ffs(m) - 1;
            unsigned bp = 0;
            if (lane == leader) bp = atomicAdd(&g_cntG[t], (unsigned)__popc(m));
            bp = __shfl_sync(FULLMASK, bp, leader);
            if (act && inG) {
                unsigned d = bp + (unsigned)__popc(m & ((1u << lane) - 1u));
                if (d < CAP) { g_keyG[t][d] = k1; g_othG[t][d] = k2; g_xyG[t][d] = x; }
            }
        }
        m = __ballot_sync(FULLMASK, act && inB);
        if (m) {
            int leader = __ffs(m) - 1;
            unsigned bp = 0;
            if (lane == leader) bp = atomicAdd(&g_cntB[t], (unsigned)__popc(m));
            bp = __shfl_sync(FULLMASK, bp, leader);
            if (act && inB) {
                unsigned d = bp + (unsigned)__popc(m & ((1u << lane) - 1u));
                if (d < CAP) { g_keyB[t][d] = k2; g_othB[t][d] = k1; g_xyB[t][d] = x; }
            }
        }
    }
    __syncthreads();
    if (threadIdx.x < 16) {
        unsigned v = h16G[threadIdx.x];
        if (v) atomicAdd(&g_h16[t][0][threadIdx.x], v);
        v = h16B[threadIdx.x];
        if (v) atomicAdd(&g_h16[t][1][threadIdx.x], v);
    }

    // ---- reconstruct sums, warp reduce, one atomic set per warp ----
    int cnt = ac.cnt, nA = ac.nA, nBB = ac.nBB;
    float sg  = ((ac.sgA0 + ac.sgA1) + (ac.sgA2 + ac.sgA3));
    float sgx = (float)x0 * sg + (ac.sgA1 + 2.0f * ac.sgA2 + 3.0f * ac.sgA3);
    float sgy = ac.sgy;
    #pragma unroll
    for (int o = 16; o; o >>= 1) {
        cnt += __shfl_down_sync(FULLMASK, cnt, o);
        nA  += __shfl_down_sync(FULLMASK, nA,  o);
        nBB += __shfl_down_sync(FULLMASK, nBB, o);
        sg  += __shfl_down_sync(FULLMASK, sg,  o);
        sgx += __shfl_down_sync(FULLMASK, sgx, o);
        sgy += __shfl_down_sync(FULLMASK, sgy, o);
    }
    if (lane == 0) {
        atomicAdd(&g_aux[t][0], (unsigned)nA);
        atomicAdd(&g_aux[t][1], (unsigned)nBB);
        atomicAdd(&g_acc[t][0], (double)cnt);
        atomicAdd(&g_acc[t][1], (double)sg);
        atomicAdd(&g_acc[t][2], (double)sgx);
        atomicAdd(&g_acc[t][3], (double)sgy);
    }
}

// ------- K4a: exact thresholds (2 vectorized buffer passes, 1024 threads) -------
__global__ void __launch_bounds__(TPB_T) k_thresh() {
    __shared__ unsigned h[4096];
    __shared__ unsigned toff[256];
    __shared__ int s_bin;
    __shared__ unsigned s_rem;
    __shared__ int sh_b1;
    __shared__ unsigned sh_r1;
    const int t = blockIdx.x;
    const int w = blockIdx.y;                 // 0 = G(gm2), 1 = B(|f|)
    const unsigned* __restrict__ key = w ? g_keyB[t] : g_keyG[t];
    const unsigned cnt = min(w ? g_cntB[t] : g_cntG[t], (unsigned)CAP);
    const int L = w ? g_sel[t].z : g_sel[t].x;
    const int tid = threadIdx.x;

    if (tid == 0) {
        long long below;
        if (w == 0) {
            // belowG = NPIX - inG_exact - aboveG_exact
            below = (long long)NPIX - (long long)g_cntG[t] - (long long)g_aux[t][0];
        } else {
            below = (long long)g_aux[t][1];
        }
        long long r = (long long)(w ? KB_RANK : KG_RANK) - below;
        if (r < 0) r = 0;
        if (r > (long long)cnt - 1) r = (long long)cnt - 1;
        unsigned run = 0; int b1 = L; unsigned r1 = (unsigned)r;
        for (int i = 0; i < 16; i++) {
            unsigned c = g_h16[t][w][i];
            if ((unsigned)r < run + c) { b1 = L + i; r1 = (unsigned)r - run; break; }
            run += c;
        }
        sh_b1 = b1; sh_r1 = r1;
    }
    __syncthreads();
    const unsigned b1 = (unsigned)sh_b1;
    const unsigned r1 = sh_r1;

    const unsigned nv4 = cnt >> 2;
    const unsigned tail = nv4 << 2;
    const uint4* __restrict__ key4 = (const uint4*)key;

    // level 1: bits 8..19 within bin b1
    for (int i = tid; i < 4096; i += TPB_T) h[i] = 0;
    __syncthreads();
    for (unsigned u = tid; u < nv4; u += TPB_T) {
        uint4 k4 = key4[u];
        if ((k4.x >> 20) == b1) atomicAdd(&h[(k4.x >> 8) & 0xFFFu], 1u);
        if ((k4.y >> 20) == b1) atomicAdd(&h[(k4.y >> 8) & 0xFFFu], 1u);
        if ((k4.z >> 20) == b1) atomicAdd(&h[(k4.z >> 8) & 0xFFFu], 1u);
        if ((k4.w >> 20) == b1) atomicAdd(&h[(k4.w >> 8) & 0xFFFu], 1u);
    }
    if ((unsigned)tid < cnt - tail) {
        unsigned k = key[tail + tid];
        if ((k >> 20) == b1) atomicAdd(&h[(k >> 8) & 0xFFFu], 1u);
    }
    __syncthreads();
    kth_bin<4096>(h, r1, toff, &s_bin, &s_rem);
    int b2 = s_bin; unsigned r2 = s_rem;
    __syncthreads();
    // level 2: low 8 bits
    for (int i = tid; i < 256; i += TPB_T) h[i] = 0;
    __syncthreads();
    unsigned pref = (b1 << 12) | (unsigned)b2;
    for (unsigned u = tid; u < nv4; u += TPB_T) {
        uint4 k4 = key4[u];
        if ((k4.x >> 8) == pref) atomicAdd(&h[k4.x & 0xFFu], 1u);
        if ((k4.y >> 8) == pref) atomicAdd(&h[k4.y & 0xFFu], 1u);
        if ((k4.z >> 8) == pref) atomicAdd(&h[k4.z & 0xFFu], 1u);
        if ((k4.w >> 8) == pref) atomicAdd(&h[k4.w & 0xFFu], 1u);
    }
    if ((unsigned)tid < cnt - tail) {
        unsigned k = key[tail + tid];
        if ((k >> 8) == pref) atomicAdd(&h[k & 0xFFu], 1u);
    }
    __syncthreads();
    kth_bin<256>(h, r2, toff, &s_bin, &s_rem);
    unsigned thr = (pref << 8) | (unsigned)s_bin;
    if (tid == 0) {
        if (w == 0) {
            // widen: reference mask is sqrtf(gm2) > sqrtf(thr2)
            float s = __fsqrt_rn(__uint_as_float(thr));
            unsigned k = thr;
            for (int i = 0; i < 64; i++) {
                if (__fsqrt_rn(__uint_as_float(k + 1u)) == s) k++;
                else break;
            }
            g_thr[t][0] = k;
        } else {
            g_thr[t][1] = thr;
        }
    }
}

// ---------------- K4b: resolve ambiguous pixels exactly (vectorized) ------------
__global__ void __launch_bounds__(TPB) k_apply() {
    const int t = blockIdx.x;
    const int q = blockIdx.y;            // NSLICE slices per frame
    const unsigned thrG = g_thr[t][0];
    const unsigned thrB = g_thr[t][1];
    const unsigned Hg = (unsigned)g_sel[t].y;
    const unsigned cG = min(g_cntG[t], (unsigned)CAP);
    const unsigned cB = min(g_cntB[t], (unsigned)CAP);

    int   cnt = 0;
    float sg = 0.f, sgx = 0.f, sgy = 0.f;

    // --- G side ---
    {
        const uint4* __restrict__ k4p = (const uint4*)g_keyG[t];
        const uint4* __restrict__ o4p = (const uint4*)g_othG[t];
        const unsigned nv4 = cG >> 2, tail = nv4 << 2;
        for (unsigned u = q * TPB + threadIdx.x; u < nv4; u += TPB * NSLICE) {
            uint4 k4 = k4p[u];
            uint4 o4 = o4p[u];
            unsigned kk[4] = {k4.x, k4.y, k4.z, k4.w};
            unsigned oo[4] = {o4.x, o4.y, o4.z, o4.w};
            #pragma unroll
            for (int j = 0; j < 4; j++) {
                if (kk[j] > thrG && oo[j] < thrB) {
                    unsigned xy = g_xyG[t][u * 4 + j];
                    float gm = __fsqrt_rn(__uint_as_float(kk[j]));
                    cnt++;
                    sg  += gm;
                    sgx += gm * (float)(xy & 1023u);
                    sgy += gm * (float)(xy >> 10);
                }
            }
        }
        if (q == 0 && (unsigned)threadIdx.x < cG - tail) {
            unsigned i = tail + threadIdx.x;
            unsigned k = g_keyG[t][i], o = g_othG[t][i];
            if (k > thrG && o < thrB) {
                unsigned xy = g_xyG[t][i];
                float gm = __fsqrt_rn(__uint_as_float(k));
                cnt++;
                sg  += gm;
                sgx += gm * (float)(xy & 1023u);
                sgy += gm * (float)(xy >> 10);
            }
        }
    }
    // --- B side (only pixels with gbin strictly above the G bracket) ---
    {
        const uint4* __restrict__ k4p = (const uint4*)g_keyB[t];
        const uint4* __restrict__ o4p = (const uint4*)g_othB[t];
        const unsigned nv4 = cB >> 2, tail = nv4 << 2;
        for (unsigned u = q * TPB + threadIdx.x; u < nv4; u += TPB * NSLICE) {
            uint4 k4 = k4p[u];
            uint4 o4 = o4p[u];
            unsigned kk[4] = {k4.x, k4.y, k4.z, k4.w};
            unsigned oo[4] = {o4.x, o4.y, o4.z, o4.w};
            #pragma unroll
            for (int j = 0; j < 4; j++) {
                if ((oo[j] >> 20) > Hg && oo[j] > thrG && kk[j] < thrB) {
                    unsigned xy = g_xyB[t][u * 4 + j];
                    float gm = __fsqrt_rn(__uint_as_float(oo[j]));
                    cnt++;
                    sg  += gm;
                    sgx += gm * (float)(xy & 1023u);
                    sgy += gm * (float)(xy >> 10);
                }
            }
        }
        if (q == 0 && (unsigned)threadIdx.x < cB - tail) {
            unsigned i = tail + threadIdx.x;
            unsigned k = g_keyB[t][i], o = g_othB[t][i];
            if ((o >> 20) > Hg && o > thrG && k < thrB) {
                unsigned xy = g_xyB[t][i];
                float gm = __fsqrt_rn(__uint_as_float(o));
                cnt++;
                sg  += gm;
                sgx += gm * (float)(xy & 1023u);
                sgy += gm * (float)(xy >> 10);
            }
        }
    }
    #pragma unroll
    for (int o = 16; o; o >>= 1) {
        cnt += __shfl_down_sync(FULLMASK, cnt, o);
        sg  += __shfl_down_sync(FULLMASK, sg,  o);
        sgx += __shfl_down_sync(FULLMASK, sgx, o);
        sgy += __shfl_down_sync(FULLMASK, sgy, o);
    }
    if ((threadIdx.x & 31) == 0) {
        atomicAdd(&g_acc[t][0], (double)cnt);
        atomicAdd(&g_acc[t][1], (double)sg);
        atomicAdd(&g_acc[t][2], (double)sgx);
        atomicAdd(&g_acc[t][3], (double)sgy);
    }
}

// ------------- block reduction over 64 doubles (64 threads) ---------------------
__device__ __forceinline__ double bred64(double v, double* red) {
    int t = threadIdx.x;
    red[t] = v;
    __syncthreads();
    for (int s = 32; s > 0; s >>= 1) {
        if (t < s) red[t] += red[t + s];
        __syncthreads();
    }
    double r = red[0];
    __syncthreads();
    return r;
}

// ---------------- K5: depthwise conv + final 8 stats (64 threads) ---------------
__global__ void k_final(const float* __restrict__ conv_w,
                        const float* __restrict__ conv_b,
                        float* __restrict__ out) {
    __shared__ double sst[4][T_FRAMES];
    __shared__ double sy[4][T_FRAMES];
    __shared__ double red[T_FRAMES];
    const int t = threadIdx.x;   // 64 threads
    const int n = T_FRAMES;
    {
        double c = g_acc[t][0], sg = g_acc[t][1], sgx = g_acc[t][2], sgy = g_acc[t][3];
        double pil = c < 1e-6 ? 1e-6 : c;
        double ws  = sg < 1e-6 ? 1e-6 : sg;
        sst[0][t] = c / (double)NPIX;
        sst[1][t] = sg / pil;
        sst[2][t] = sgx / ws / (double)W_DIM;
        sst[3][t] = sgy / ws / (double)H_DIM;
    }
    __syncthreads();
    #pragma unroll
    for (int c = 0; c < 4; c++) {
        double v = (double)conv_b[c] + (double)conv_w[c * 3 + 1] * sst[c][t];
        if (t > 0)     v += (double)conv_w[c * 3 + 0] * sst[c][t - 1];
        if (t < n - 1) v += (double)conv_w[c * 3 + 2] * sst[c][t + 1];
        sy[c][t] = v;
    }
    __syncthreads();

    double lm = bred64(sy[0][t], red) / n;
    double im = bred64(sy[1][t], red) / n;
    double tn = (double)t / (double)(n - 1) - 0.5;
    double lt  = bred64((sy[0][t] - lm) * tn, red) * 6.0 / n;
    double itr = bred64((sy[1][t] - im) * tn, red) * 6.0 / n;

    double dx = 0.0, dy = 0.0, sp = 0.0;
    if (t < n - 1) {
        dx = sy[2][t + 1] - sy[2][t];
        dy = sy[3][t + 1] - sy[3][t];
        sp = sqrt(dx * dx + dy * dy);
    }
    double sdx  = bred64(dx, red);
    double sdy  = bred64(dy, red);
    double ssum = bred64(sp, red);
    double ms = ssum / (double)(n - 1);
    double var = bred64(t < n - 1 ? (sp - ms) * (sp - ms) : 0.0, red) / (double)(n - 2);

    if (t == 0) {
        out[0] = (float)lm;
        out[1] = (float)lt;
        out[2] = (float)im;
        out[3] = (float)itr;
        out[4] = (float)ms;
        out[5] = (float)(atan2(sdy, sdx) / 3.14159265358979323846);
        out[6] = (float)((sy[0][n - 1] - sy[0][0]) / (double)(n - 1));
        out[7] = (float)sqrt(var);
    }
}

// ---------------- entry point -----------------------------------------------------
extern "C" void kernel_launch(void* const* d_in, const int* in_sizes, int n_in,
                              void* d_out, int out_size) {
    const float* frames = (const float*)d_in[0];
    // d_in[1] = observed_mask (unused by reference)
    const float* conv_w = (const float*)d_in[2];
    const float* conv_b = (const float*)d_in[3];
    float* out = (float*)d_out;

    k_shist<<<dim3(SH_BLOCKS, T_FRAMES), TPB>>>(frames);
    k_bracket<<<T_FRAMES, TPB>>>();
    k_main<<<dim3(MCHUNKS, T_FRAMES), TPB>>>(frames);
    k_thresh<<<dim3(T_FRAMES, 2), TPB_T>>>();
    k_apply<<<dim3(T_FRAMES, NSLICE), TPB>>>();
    k_final<<<1, T_FRAMES>>>(conv_w, conv_b, out);
}